// round 1
// baseline (speedup 1.0000x reference)
#include <cuda_runtime.h>
#include <math.h>

// Problem constants
#define NB    2
#define TSEQ  2048
#define CDIM  2048
#define NH    16
#define NKV   4
#define HD    128
#define MROWS (NB * TSEQ)          // 4096
#define KVW   (2 * NKV * HD)       // 1024

// Scratch (no cudaMalloc allowed)
__device__ float g_Q[(size_t)MROWS * CDIM];   // [B*T, H*D]
__device__ float g_KV[(size_t)MROWS * KVW];   // [B*T, 2*KV*D]
__device__ float g_Y[(size_t)MROWS * CDIM];   // attention output [B*T, H*D]

// ---------------------------------------------------------------------------
// NT GEMM: C[M,N] = A[M,K] * B[N,K]^T   (both row-major, dot of rows)
// Tile 128x128, BK=16, 256 threads, 8x8 per-thread microkernel.
// M,N,K all multiples of the tile sizes here (no bounds checks).
// ---------------------------------------------------------------------------
__global__ __launch_bounds__(256) void gemm_nt_kernel(
    const float* __restrict__ A, const float* __restrict__ B,
    float* __restrict__ C, int M, int N, int K)
{
    __shared__ float As[16][132];
    __shared__ float Bs[16][132];

    const int tid = threadIdx.x;
    const int bm = blockIdx.y * 128;
    const int bn = blockIdx.x * 128;
    const int tm = tid >> 4;          // 0..15
    const int tn = tid & 15;          // 0..15
    const int lr = tid >> 2;          // 0..63 (row within half-tile)
    const int lk = (tid & 3) * 4;     // 0,4,8,12 (k offset)

    const float* Abase = A + (size_t)(bm + lr) * K + lk;
    const float* Bbase = B + (size_t)(bn + lr) * K + lk;

    float acc[8][8];
#pragma unroll
    for (int i = 0; i < 8; i++)
#pragma unroll
        for (int j = 0; j < 8; j++) acc[i][j] = 0.f;

    for (int k0 = 0; k0 < K; k0 += 16) {
        float4 a0 = *(const float4*)(Abase + k0);
        float4 a1 = *(const float4*)(Abase + (size_t)64 * K + k0);
        float4 b0 = *(const float4*)(Bbase + k0);
        float4 b1 = *(const float4*)(Bbase + (size_t)64 * K + k0);

        __syncthreads();   // previous iteration's compute done before overwrite
        As[lk + 0][lr] = a0.x; As[lk + 1][lr] = a0.y;
        As[lk + 2][lr] = a0.z; As[lk + 3][lr] = a0.w;
        As[lk + 0][lr + 64] = a1.x; As[lk + 1][lr + 64] = a1.y;
        As[lk + 2][lr + 64] = a1.z; As[lk + 3][lr + 64] = a1.w;
        Bs[lk + 0][lr] = b0.x; Bs[lk + 1][lr] = b0.y;
        Bs[lk + 2][lr] = b0.z; Bs[lk + 3][lr] = b0.w;
        Bs[lk + 0][lr + 64] = b1.x; Bs[lk + 1][lr + 64] = b1.y;
        Bs[lk + 2][lr + 64] = b1.z; Bs[lk + 3][lr + 64] = b1.w;
        __syncthreads();

#pragma unroll
        for (int kk = 0; kk < 16; kk++) {
            float a[8], b[8];
            *(float4*)(a)     = *(const float4*)&As[kk][tm * 4];
            *(float4*)(a + 4) = *(const float4*)&As[kk][tm * 4 + 64];
            *(float4*)(b)     = *(const float4*)&Bs[kk][tn * 4];
            *(float4*)(b + 4) = *(const float4*)&Bs[kk][tn * 4 + 64];
#pragma unroll
            for (int i = 0; i < 8; i++)
#pragma unroll
                for (int j = 0; j < 8; j++)
                    acc[i][j] = fmaf(a[i], b[j], acc[i][j]);
        }
    }

#pragma unroll
    for (int i = 0; i < 8; i++) {
        int r = bm + tm * 4 + ((i < 4) ? i : 60 + i);   // rows tm*4+{0..3}, tm*4+64+{0..3}
        float4 o0 = make_float4(acc[i][0], acc[i][1], acc[i][2], acc[i][3]);
        float4 o1 = make_float4(acc[i][4], acc[i][5], acc[i][6], acc[i][7]);
        *(float4*)&C[(size_t)r * N + bn + tn * 4]      = o0;
        *(float4*)&C[(size_t)r * N + bn + tn * 4 + 64] = o1;
    }
}

// ---------------------------------------------------------------------------
// RoPE: in-place on X with layout [rows, ..., nheads, 128], row stride given.
// rows = B*T, t = row % T. Pair (i, i+64), i < 64.
//   new[i]    = x[i]*cos - x[i+64]*sin
//   new[i+64] = x[i+64]*cos + x[i]*sin
// ---------------------------------------------------------------------------
__global__ void rope_kernel(float* __restrict__ X, int rows, int nheads, int rowstride)
{
    int idx = blockIdx.x * blockDim.x + threadIdx.x;
    int total = rows * nheads * 64;
    if (idx >= total) return;
    int i   = idx & 63;
    int h   = (idx >> 6) % nheads;
    int row = idx / (64 * nheads);
    int t   = row & (TSEQ - 1);

    // freq_i = 10000^(-i/64) = exp(-i * ln(10000)/64)
    float freq = expf(-(float)i * (9.210340371976184f / 64.0f));
    float ang = (float)t * freq;
    float s, c;
    sincosf(ang, &s, &c);

    float* p = X + (size_t)row * rowstride + h * 128;
    float x0 = p[i];
    float x1 = p[i + 64];
    p[i]      = x0 * c - x1 * s;
    p[i + 64] = x1 * c + x0 * s;
}

// ---------------------------------------------------------------------------
// Causal flash attention (fp32).
// Grid: (T/64, H, B). 128 threads. Br=64 query rows, Bc=32 key cols per tile.
// Thread layout: warp w owns rows w*16..w*16+15; lanes 0-15 = dims 0-63,
// lanes 16-31 = dims 64-127 of the same rows (partner = lane^16).
// q and acc live in registers (64 floats each); K/V tiles stream via smem.
// ---------------------------------------------------------------------------
__global__ __launch_bounds__(128) void attn_kernel(
    const float* __restrict__ Q, const float* __restrict__ KV,
    float* __restrict__ Y)
{
    __shared__ float Ks[32][128];
    __shared__ float Vs[32][128];

    const int b  = blockIdx.z;
    const int h  = blockIdx.y;
    const int q0 = blockIdx.x * 64;
    const int kvh = h >> 2;               // GQA: 4 query heads per kv head
    const int tid  = threadIdx.x;
    const int warp = tid >> 5;
    const int lane = tid & 31;
    const int row  = warp * 16 + (lane & 15);
    const int half = lane >> 4;
    const int qi = q0 + row;

    const float scale = 0.08838834764831845f;   // 1/sqrt(128)

    // load q row-half into registers
    float4 q4[16];
    {
        const float* qp = Q + (size_t)(b * TSEQ + qi) * CDIM + h * 128 + half * 64;
#pragma unroll
        for (int i = 0; i < 16; i++) q4[i] = *(const float4*)(qp + i * 4);
    }

    float4 acc[16];
#pragma unroll
    for (int i = 0; i < 16; i++) acc[i] = make_float4(0.f, 0.f, 0.f, 0.f);
    float m = -1e30f, l = 0.f;

    const int ntiles = q0 / 32 + 2;   // keys up to q0+63

    for (int tIdx = 0; tIdx < ntiles; tIdx++) {
        const int s0 = tIdx * 32;

        __syncthreads();   // previous tile's smem reads done
        // load K,V tiles: 32x128 each; 128 threads x 8 float4 per buffer
#pragma unroll
        for (int i = 0; i < 8; i++) {
            int lin = tid * 4 + i * 512;            // float index in 32x128
            int r = lin >> 7, d = lin & 127;
            const float* base = KV + (size_t)(b * TSEQ + s0 + r) * KVW + kvh * 128 + d;
            *(float4*)&Ks[r][d] = *(const float4*)base;
            *(float4*)&Vs[r][d] = *(const float4*)(base + NKV * HD);  // V at +512
        }
        __syncthreads();

        float s[32];
#pragma unroll
        for (int j = 0; j < 32; j++) {
            const float4* krow = (const float4*)&Ks[j][half * 64];
            float d0 = 0.f, d1 = 0.f, d2 = 0.f, d3 = 0.f;
#pragma unroll
            for (int i = 0; i < 16; i++) {
                float4 k = krow[i];
                d0 = fmaf(q4[i].x, k.x, d0);
                d1 = fmaf(q4[i].y, k.y, d1);
                d2 = fmaf(q4[i].z, k.z, d2);
                d3 = fmaf(q4[i].w, k.w, d3);
            }
            float d = (d0 + d1) + (d2 + d3);
            d += __shfl_xor_sync(0xffffffffu, d, 16);   // combine the two halves
            s[j] = (s0 + j <= qi) ? d * scale : -1e30f;
        }

        float mt = m;
#pragma unroll
        for (int j = 0; j < 32; j++) mt = fmaxf(mt, s[j]);
        float corr = expf(m - mt);
        m = mt;
        l *= corr;
#pragma unroll
        for (int i = 0; i < 16; i++) {
            acc[i].x *= corr; acc[i].y *= corr; acc[i].z *= corr; acc[i].w *= corr;
        }

#pragma unroll
        for (int j = 0; j < 32; j++) {
            float p = expf(s[j] - m);
            l += p;
            const float4* vrow = (const float4*)&Vs[j][half * 64];
#pragma unroll
            for (int i = 0; i < 16; i++) {
                float4 v = vrow[i];
                acc[i].x = fmaf(p, v.x, acc[i].x);
                acc[i].y = fmaf(p, v.y, acc[i].y);
                acc[i].z = fmaf(p, v.z, acc[i].z);
                acc[i].w = fmaf(p, v.w, acc[i].w);
            }
        }
    }

    float inv = 1.f / l;
    float* op = Y + (size_t)(b * TSEQ + qi) * CDIM + h * 128 + half * 64;
#pragma unroll
    for (int i = 0; i < 16; i++) {
        float4 o = make_float4(acc[i].x * inv, acc[i].y * inv, acc[i].z * inv, acc[i].w * inv);
        *(float4*)(op + i * 4) = o;
    }
}

// ---------------------------------------------------------------------------
extern "C" void kernel_launch(void* const* d_in, const int* in_sizes, int n_in,
                              void* d_out, int out_size)
{
    const float* x   = (const float*)d_in[0];   // [B,T,C]
    const float* Wq  = (const float*)d_in[1];   // [H*D, C]
    const float* Wkv = (const float*)d_in[2];   // [2*KV*D, C]
    const float* Wo  = (const float*)d_in[3];   // [C, C]
    float* out = (float*)d_out;

    float *pQ, *pKV, *pY;
    cudaGetSymbolAddress((void**)&pQ,  g_Q);
    cudaGetSymbolAddress((void**)&pKV, g_KV);
    cudaGetSymbolAddress((void**)&pY,  g_Y);

    // 1) Q = x @ Wq^T  : [4096, 2048]
    gemm_nt_kernel<<<dim3(CDIM / 128, MROWS / 128), 256>>>(x, Wq, pQ, MROWS, CDIM, CDIM);
    // 2) KV = x @ Wkv^T : [4096, 1024]
    gemm_nt_kernel<<<dim3(KVW / 128, MROWS / 128), 256>>>(x, Wkv, pKV, MROWS, KVW, CDIM);

    // 3) RoPE on Q (16 heads, stride 2048) and K (first 4 head-slots of KV, stride 1024)
    {
        int totQ = MROWS * NH * 64;
        rope_kernel<<<(totQ + 255) / 256, 256>>>(pQ, MROWS, NH, CDIM);
        int totK = MROWS * NKV * 64;
        rope_kernel<<<(totK + 255) / 256, 256>>>(pKV, MROWS, NKV, KVW);
    }

    // 4) causal flash attention -> g_Y
    attn_kernel<<<dim3(TSEQ / 64, NH, NB), 128>>>(pQ, pKV, pY);

    // 5) out = Y @ Wo^T : [4096, 2048]
    gemm_nt_kernel<<<dim3(CDIM / 128, MROWS / 128), 256>>>(pY, Wo, out, MROWS, CDIM, CDIM);
}

// round 2
// speedup vs baseline: 1.3066x; 1.3066x over previous
#include <cuda_runtime.h>
#include <math.h>
#include <stdint.h>

// Problem constants
#define NB    2
#define TSEQ  2048
#define CDIM  2048
#define NH    16
#define NKV   4
#define HD    128
#define MROWS (NB * TSEQ)          // 4096
#define KVW   (2 * NKV * HD)       // 1024

// Scratch (no cudaMalloc allowed)
__device__ float g_Q[(size_t)MROWS * CDIM];   // [B*T, H*D]
__device__ float g_KV[(size_t)MROWS * KVW];   // [B*T, 2*KV*D]
__device__ float g_Y[(size_t)MROWS * CDIM];   // attention output [B*T, H*D]

// ---------------------------------------------------------------------------
// TF32 tensor-core NT GEMM: C[M,N] = A[M,K] * B[N,K]^T  (row-major, row dots)
// 128x128 tile, BK=32, 256 threads (8 warps in 2x4), warp tile 64x32,
// mma.sync.aligned.m16n8k8.tf32, cp.async double-buffered smem.
// Requires M%128==0, N%128==0, K%32==0.
// ---------------------------------------------------------------------------
#define BKG   32
#define PADK  36                       // 32 + 4 pad -> conflict-free frag LDS
#define TILEF (128 * PADK)             // floats per smem tile

__device__ __forceinline__ uint32_t f2tf32(float x) {
    uint32_t r;
    asm("cvt.rna.tf32.f32 %0, %1;\n" : "=r"(r) : "f"(x));
    return r;
}

__device__ __forceinline__ void mma_tf32(float* c,
                                         uint32_t a0, uint32_t a1, uint32_t a2, uint32_t a3,
                                         uint32_t b0, uint32_t b1) {
    asm("mma.sync.aligned.m16n8k8.row.col.f32.tf32.tf32.f32 "
        "{%0,%1,%2,%3}, {%4,%5,%6,%7}, {%8,%9}, {%0,%1,%2,%3};\n"
        : "+f"(c[0]), "+f"(c[1]), "+f"(c[2]), "+f"(c[3])
        : "r"(a0), "r"(a1), "r"(a2), "r"(a3), "r"(b0), "r"(b1));
}

__device__ __forceinline__ void cp_async16(uint32_t smem_addr, const float* gptr) {
    asm volatile("cp.async.cg.shared.global [%0], [%1], 16;\n"
                 :: "r"(smem_addr), "l"(gptr));
}

__global__ __launch_bounds__(256, 2) void gemm_tf32_nt(
    const float* __restrict__ A, const float* __restrict__ B,
    float* __restrict__ C, int M, int N, int K)
{
    extern __shared__ float sm[];
    float* Abuf[2] = { sm,             sm + TILEF };
    float* Bbuf[2] = { sm + 2*TILEF,   sm + 3*TILEF };

    const int tid  = threadIdx.x;
    const int bm   = blockIdx.y * 128;
    const int bn   = blockIdx.x * 128;
    const int warp = tid >> 5;
    const int lane = tid & 31;
    const int wm   = warp >> 2;        // 0..1  (64-row slab)
    const int wn   = warp & 3;         // 0..3  (32-col slab)
    const int gid  = lane >> 2;        // 0..7
    const int tig  = lane & 3;         // 0..3

    // copy indexing: each thread copies one half-row (16 floats) of A and B
    const int crow  = tid >> 1;        // 0..127
    const int cquad = tid & 1;         // 0..1
    const float* gA = A + (size_t)(bm + crow) * K + cquad * 16;
    const float* gB = B + (size_t)(bn + crow) * K + cquad * 16;
    const int soff  = crow * PADK + cquad * 16;

    float acc[4][4][4];                // [mt][nt][4]
#pragma unroll
    for (int mt = 0; mt < 4; mt++)
#pragma unroll
        for (int nt = 0; nt < 4; nt++)
#pragma unroll
            for (int i = 0; i < 4; i++) acc[mt][nt][i] = 0.f;

    const int niter = K / BKG;

    // prefetch tile 0
    {
        uint32_t sa = (uint32_t)__cvta_generic_to_shared(Abuf[0] + soff);
        uint32_t sb = (uint32_t)__cvta_generic_to_shared(Bbuf[0] + soff);
#pragma unroll
        for (int i = 0; i < 4; i++) {
            cp_async16(sa + i * 16, gA + i * 4);
            cp_async16(sb + i * 16, gB + i * 4);
        }
        asm volatile("cp.async.commit_group;\n" ::: "memory");
    }

    for (int k0 = 0; k0 < niter; k0++) {
        const int buf = k0 & 1;
        // prefetch next tile into buf^1
        if (k0 + 1 < niter) {
            const int koff = (k0 + 1) * BKG;
            uint32_t sa = (uint32_t)__cvta_generic_to_shared(Abuf[buf ^ 1] + soff);
            uint32_t sb = (uint32_t)__cvta_generic_to_shared(Bbuf[buf ^ 1] + soff);
#pragma unroll
            for (int i = 0; i < 4; i++) {
                cp_async16(sa + i * 16, gA + koff + i * 4);
                cp_async16(sb + i * 16, gB + koff + i * 4);
            }
        }
        asm volatile("cp.async.commit_group;\n" ::: "memory");
        asm volatile("cp.async.wait_group 1;\n" ::: "memory");
        __syncthreads();

        const float* As = Abuf[buf];
        const float* Bs = Bbuf[buf];
#pragma unroll
        for (int ks = 0; ks < 4; ks++) {
            const int kc = ks * 8;
            uint32_t af[4][4], bf[4][2];
#pragma unroll
            for (int mt = 0; mt < 4; mt++) {
                const int r = wm * 64 + mt * 16 + gid;
                af[mt][0] = f2tf32(As[r * PADK + kc + tig]);
                af[mt][1] = f2tf32(As[(r + 8) * PADK + kc + tig]);
                af[mt][2] = f2tf32(As[r * PADK + kc + tig + 4]);
                af[mt][3] = f2tf32(As[(r + 8) * PADK + kc + tig + 4]);
            }
#pragma unroll
            for (int nt = 0; nt < 4; nt++) {
                const int r = wn * 32 + nt * 8 + gid;
                bf[nt][0] = f2tf32(Bs[r * PADK + kc + tig]);
                bf[nt][1] = f2tf32(Bs[r * PADK + kc + tig + 4]);
            }
#pragma unroll
            for (int mt = 0; mt < 4; mt++)
#pragma unroll
                for (int nt = 0; nt < 4; nt++)
                    mma_tf32(acc[mt][nt], af[mt][0], af[mt][1], af[mt][2], af[mt][3],
                             bf[nt][0], bf[nt][1]);
        }
        __syncthreads();
    }

    // epilogue: c0/c1 at (row, col..col+1), c2/c3 at (row+8, ..)
#pragma unroll
    for (int mt = 0; mt < 4; mt++) {
        const int r0 = bm + wm * 64 + mt * 16 + gid;
#pragma unroll
        for (int nt = 0; nt < 4; nt++) {
            const int c0 = bn + wn * 32 + nt * 8 + tig * 2;
            *(float2*)&C[(size_t)r0 * N + c0]       = make_float2(acc[mt][nt][0], acc[mt][nt][1]);
            *(float2*)&C[(size_t)(r0 + 8) * N + c0] = make_float2(acc[mt][nt][2], acc[mt][nt][3]);
        }
    }
}

// ---------------------------------------------------------------------------
// RoPE: in-place, layout [rows, nheads, 128], given row stride (floats).
// ---------------------------------------------------------------------------
__global__ void rope_kernel(float* __restrict__ X, int rows, int nheads, int rowstride)
{
    int idx = blockIdx.x * blockDim.x + threadIdx.x;
    int total = rows * nheads * 64;
    if (idx >= total) return;
    int i   = idx & 63;
    int h   = (idx >> 6) % nheads;
    int row = idx / (64 * nheads);
    int t   = row & (TSEQ - 1);

    float freq = expf(-(float)i * (9.210340371976184f / 64.0f));
    float ang = (float)t * freq;
    float s, c;
    sincosf(ang, &s, &c);

    float* p = X + (size_t)row * rowstride + h * 128;
    float x0 = p[i];
    float x1 = p[i + 64];
    p[i]      = x0 * c - x1 * s;
    p[i + 64] = x1 * c + x0 * s;
}

// ---------------------------------------------------------------------------
// Causal flash attention (fp32, FFMA). Grid: (T/64, H, B), 128 threads.
// ---------------------------------------------------------------------------
__global__ __launch_bounds__(128) void attn_kernel(
    const float* __restrict__ Q, const float* __restrict__ KV,
    float* __restrict__ Y)
{
    __shared__ float Ks[32][128];
    __shared__ float Vs[32][128];

    const int b  = blockIdx.z;
    const int h  = blockIdx.y;
    const int q0 = blockIdx.x * 64;
    const int kvh = h >> 2;
    const int tid  = threadIdx.x;
    const int warp = tid >> 5;
    const int lane = tid & 31;
    const int row  = warp * 16 + (lane & 15);
    const int half = lane >> 4;
    const int qi = q0 + row;

    const float scale = 0.08838834764831845f;   // 1/sqrt(128)

    float4 q4[16];
    {
        const float* qp = Q + (size_t)(b * TSEQ + qi) * CDIM + h * 128 + half * 64;
#pragma unroll
        for (int i = 0; i < 16; i++) q4[i] = *(const float4*)(qp + i * 4);
    }

    float4 acc[16];
#pragma unroll
    for (int i = 0; i < 16; i++) acc[i] = make_float4(0.f, 0.f, 0.f, 0.f);
    float m = -1e30f, l = 0.f;

    const int ntiles = q0 / 32 + 2;

    for (int tIdx = 0; tIdx < ntiles; tIdx++) {
        const int s0 = tIdx * 32;

        __syncthreads();
#pragma unroll
        for (int i = 0; i < 8; i++) {
            int lin = tid * 4 + i * 512;
            int r = lin >> 7, d = lin & 127;
            const float* base = KV + (size_t)(b * TSEQ + s0 + r) * KVW + kvh * 128 + d;
            *(float4*)&Ks[r][d] = *(const float4*)base;
            *(float4*)&Vs[r][d] = *(const float4*)(base + NKV * HD);
        }
        __syncthreads();

        float s[32];
#pragma unroll
        for (int j = 0; j < 32; j++) {
            const float4* krow = (const float4*)&Ks[j][half * 64];
            float d0 = 0.f, d1 = 0.f, d2 = 0.f, d3 = 0.f;
#pragma unroll
            for (int i = 0; i < 16; i++) {
                float4 k = krow[i];
                d0 = fmaf(q4[i].x, k.x, d0);
                d1 = fmaf(q4[i].y, k.y, d1);
                d2 = fmaf(q4[i].z, k.z, d2);
                d3 = fmaf(q4[i].w, k.w, d3);
            }
            float d = (d0 + d1) + (d2 + d3);
            d += __shfl_xor_sync(0xffffffffu, d, 16);
            s[j] = (s0 + j <= qi) ? d * scale : -1e30f;
        }

        float mt = m;
#pragma unroll
        for (int j = 0; j < 32; j++) mt = fmaxf(mt, s[j]);
        float corr = __expf(m - mt);
        m = mt;
        l *= corr;
#pragma unroll
        for (int i = 0; i < 16; i++) {
            acc[i].x *= corr; acc[i].y *= corr; acc[i].z *= corr; acc[i].w *= corr;
        }

#pragma unroll
        for (int j = 0; j < 32; j++) {
            float p = __expf(s[j] - m);
            l += p;
            const float4* vrow = (const float4*)&Vs[j][half * 64];
#pragma unroll
            for (int i = 0; i < 16; i++) {
                float4 v = vrow[i];
                acc[i].x = fmaf(p, v.x, acc[i].x);
                acc[i].y = fmaf(p, v.y, acc[i].y);
                acc[i].z = fmaf(p, v.z, acc[i].z);
                acc[i].w = fmaf(p, v.w, acc[i].w);
            }
        }
    }

    float inv = 1.f / l;
    float* op = Y + (size_t)(b * TSEQ + qi) * CDIM + h * 128 + half * 64;
#pragma unroll
    for (int i = 0; i < 16; i++) {
        float4 o = make_float4(acc[i].x * inv, acc[i].y * inv, acc[i].z * inv, acc[i].w * inv);
        *(float4*)(op + i * 4) = o;
    }
}

// ---------------------------------------------------------------------------
extern "C" void kernel_launch(void* const* d_in, const int* in_sizes, int n_in,
                              void* d_out, int out_size)
{
    const float* x   = (const float*)d_in[0];   // [B,T,C]
    const float* Wq  = (const float*)d_in[1];   // [H*D, C]
    const float* Wkv = (const float*)d_in[2];   // [2*KV*D, C]
    const float* Wo  = (const float*)d_in[3];   // [C, C]
    float* out = (float*)d_out;

    float *pQ, *pKV, *pY;
    cudaGetSymbolAddress((void**)&pQ,  g_Q);
    cudaGetSymbolAddress((void**)&pKV, g_KV);
    cudaGetSymbolAddress((void**)&pY,  g_Y);

    const int smem_bytes = 4 * TILEF * sizeof(float);   // 73728
    cudaFuncSetAttribute(gemm_tf32_nt, cudaFuncAttributeMaxDynamicSharedMemorySize, smem_bytes);

    // 1) Q = x @ Wq^T : [4096, 2048]
    gemm_tf32_nt<<<dim3(CDIM / 128, MROWS / 128), 256, smem_bytes>>>(x, Wq, pQ, MROWS, CDIM, CDIM);
    // 2) KV = x @ Wkv^T : [4096, 1024]
    gemm_tf32_nt<<<dim3(KVW / 128, MROWS / 128), 256, smem_bytes>>>(x, Wkv, pKV, MROWS, KVW, CDIM);

    // 3) RoPE on Q (16 heads, stride 2048) and K (first 4 head-slots of KV, stride 1024)
    {
        int totQ = MROWS * NH * 64;
        rope_kernel<<<(totQ + 255) / 256, 256>>>(pQ, MROWS, NH, CDIM);
        int totK = MROWS * NKV * 64;
        rope_kernel<<<(totK + 255) / 256, 256>>>(pKV, MROWS, NKV, KVW);
    }

    // 4) causal flash attention -> g_Y
    attn_kernel<<<dim3(TSEQ / 64, NH, NB), 128>>>(pQ, pKV, pY);

    // 5) out = Y @ Wo^T : [4096, 2048]
    gemm_tf32_nt<<<dim3(CDIM / 128, MROWS / 128), 256, smem_bytes>>>(pY, Wo, out, MROWS, CDIM, CDIM);
}

// round 3
// speedup vs baseline: 2.7882x; 2.1340x over previous
#include <cuda_runtime.h>
#include <math.h>
#include <stdint.h>

// Problem constants
#define NB    2
#define TSEQ  2048
#define CDIM  2048
#define NH    16
#define NKV   4
#define HD    128
#define MROWS (NB * TSEQ)          // 4096
#define KVW   (2 * NKV * HD)       // 1024

// Scratch (no cudaMalloc allowed)
__device__ float g_Q[(size_t)MROWS * CDIM];
__device__ float g_KV[(size_t)MROWS * KVW];
__device__ float g_Y[(size_t)MROWS * CDIM];

// ---------------------------------------------------------------------------
// Common mma helpers
// ---------------------------------------------------------------------------
__device__ __forceinline__ uint32_t f2tf32(float x) {
    uint32_t r;
    asm("cvt.rna.tf32.f32 %0, %1;\n" : "=r"(r) : "f"(x));
    return r;
}

__device__ __forceinline__ void mma_tf32(float* c,
                                         uint32_t a0, uint32_t a1, uint32_t a2, uint32_t a3,
                                         uint32_t b0, uint32_t b1) {
    asm("mma.sync.aligned.m16n8k8.row.col.f32.tf32.tf32.f32 "
        "{%0,%1,%2,%3}, {%4,%5,%6,%7}, {%8,%9}, {%0,%1,%2,%3};\n"
        : "+f"(c[0]), "+f"(c[1]), "+f"(c[2]), "+f"(c[3])
        : "r"(a0), "r"(a1), "r"(a2), "r"(a3), "r"(b0), "r"(b1));
}

__device__ __forceinline__ void cp_async16(uint32_t smem_addr, const float* gptr) {
    asm volatile("cp.async.cg.shared.global [%0], [%1], 16;\n"
                 :: "r"(smem_addr), "l"(gptr));
}

// ---------------------------------------------------------------------------
// TF32 tensor-core NT GEMM: C[M,N] = A[M,K] * B[N,K]^T
// ---------------------------------------------------------------------------
#define BKG   32
#define PADK  36
#define TILEF (128 * PADK)

__global__ __launch_bounds__(256, 2) void gemm_tf32_nt(
    const float* __restrict__ A, const float* __restrict__ B,
    float* __restrict__ C, int M, int N, int K)
{
    extern __shared__ float sm[];
    float* Abuf[2] = { sm,             sm + TILEF };
    float* Bbuf[2] = { sm + 2*TILEF,   sm + 3*TILEF };

    const int tid  = threadIdx.x;
    const int bm   = blockIdx.y * 128;
    const int bn   = blockIdx.x * 128;
    const int warp = tid >> 5;
    const int lane = tid & 31;
    const int wm   = warp >> 2;
    const int wn   = warp & 3;
    const int gid  = lane >> 2;
    const int tig  = lane & 3;

    const int crow  = tid >> 1;
    const int cquad = tid & 1;
    const float* gA = A + (size_t)(bm + crow) * K + cquad * 16;
    const float* gB = B + (size_t)(bn + crow) * K + cquad * 16;
    const int soff  = crow * PADK + cquad * 16;

    float acc[4][4][4];
#pragma unroll
    for (int mt = 0; mt < 4; mt++)
#pragma unroll
        for (int nt = 0; nt < 4; nt++)
#pragma unroll
            for (int i = 0; i < 4; i++) acc[mt][nt][i] = 0.f;

    const int niter = K / BKG;

    {
        uint32_t sa = (uint32_t)__cvta_generic_to_shared(Abuf[0] + soff);
        uint32_t sb = (uint32_t)__cvta_generic_to_shared(Bbuf[0] + soff);
#pragma unroll
        for (int i = 0; i < 4; i++) {
            cp_async16(sa + i * 16, gA + i * 4);
            cp_async16(sb + i * 16, gB + i * 4);
        }
        asm volatile("cp.async.commit_group;\n" ::: "memory");
    }

    for (int k0 = 0; k0 < niter; k0++) {
        const int buf = k0 & 1;
        if (k0 + 1 < niter) {
            const int koff = (k0 + 1) * BKG;
            uint32_t sa = (uint32_t)__cvta_generic_to_shared(Abuf[buf ^ 1] + soff);
            uint32_t sb = (uint32_t)__cvta_generic_to_shared(Bbuf[buf ^ 1] + soff);
#pragma unroll
            for (int i = 0; i < 4; i++) {
                cp_async16(sa + i * 16, gA + koff + i * 4);
                cp_async16(sb + i * 16, gB + koff + i * 4);
            }
        }
        asm volatile("cp.async.commit_group;\n" ::: "memory");
        asm volatile("cp.async.wait_group 1;\n" ::: "memory");
        __syncthreads();

        const float* As = Abuf[buf];
        const float* Bs = Bbuf[buf];
#pragma unroll
        for (int ks = 0; ks < 4; ks++) {
            const int kc = ks * 8;
            uint32_t af[4][4], bf[4][2];
#pragma unroll
            for (int mt = 0; mt < 4; mt++) {
                const int r = wm * 64 + mt * 16 + gid;
                af[mt][0] = f2tf32(As[r * PADK + kc + tig]);
                af[mt][1] = f2tf32(As[(r + 8) * PADK + kc + tig]);
                af[mt][2] = f2tf32(As[r * PADK + kc + tig + 4]);
                af[mt][3] = f2tf32(As[(r + 8) * PADK + kc + tig + 4]);
            }
#pragma unroll
            for (int nt = 0; nt < 4; nt++) {
                const int r = wn * 32 + nt * 8 + gid;
                bf[nt][0] = f2tf32(Bs[r * PADK + kc + tig]);
                bf[nt][1] = f2tf32(Bs[r * PADK + kc + tig + 4]);
            }
#pragma unroll
            for (int mt = 0; mt < 4; mt++)
#pragma unroll
                for (int nt = 0; nt < 4; nt++)
                    mma_tf32(acc[mt][nt], af[mt][0], af[mt][1], af[mt][2], af[mt][3],
                             bf[nt][0], bf[nt][1]);
        }
        __syncthreads();
    }

#pragma unroll
    for (int mt = 0; mt < 4; mt++) {
        const int r0 = bm + wm * 64 + mt * 16 + gid;
#pragma unroll
        for (int nt = 0; nt < 4; nt++) {
            const int c0 = bn + wn * 32 + nt * 8 + tig * 2;
            *(float2*)&C[(size_t)r0 * N + c0]       = make_float2(acc[mt][nt][0], acc[mt][nt][1]);
            *(float2*)&C[(size_t)(r0 + 8) * N + c0] = make_float2(acc[mt][nt][2], acc[mt][nt][3]);
        }
    }
}

// ---------------------------------------------------------------------------
// RoPE: in-place, layout [rows, nheads, 128], given row stride (floats).
// ---------------------------------------------------------------------------
__global__ void rope_kernel(float* __restrict__ X, int rows, int nheads, int rowstride)
{
    int idx = blockIdx.x * blockDim.x + threadIdx.x;
    int total = rows * nheads * 64;
    if (idx >= total) return;
    int i   = idx & 63;
    int h   = (idx >> 6) % nheads;
    int row = idx / (64 * nheads);
    int t   = row & (TSEQ - 1);

    float freq = expf(-(float)i * (9.210340371976184f / 64.0f));
    float ang = (float)t * freq;
    float s, c;
    sincosf(ang, &s, &c);

    float* p = X + (size_t)row * rowstride + h * 128;
    float x0 = p[i];
    float x1 = p[i + 64];
    p[i]      = x0 * c - x1 * s;
    p[i + 64] = x1 * c + x0 * s;
}

// ---------------------------------------------------------------------------
// Tensor-core causal flash attention (tf32 mma, fp32 softmax).
// Grid: (T/64, H, B), 128 threads (4 warps). Warp w owns rows w*16..w*16+15.
// Key tiles Bc=32, cp.async double-buffered K/V.
//
// Smem layout (floats): buf0: K[32*132], V[32*136]; buf1: same; Ps[64*36].
// ---------------------------------------------------------------------------
#define KPAD  132
#define VPAD  136
#define PPAD  36
#define KTILE (32 * KPAD)    // 4224
#define VTILE (32 * VPAD)    // 4352
#define BUFSZ (KTILE + VTILE)
#define ATTN_SMEM ((2 * BUFSZ + 64 * PPAD) * 4)   // 77824 bytes

__global__ __launch_bounds__(128, 2) void attn_mma_kernel(
    const float* __restrict__ Q, const float* __restrict__ KV,
    float* __restrict__ Y)
{
    extern __shared__ float sm[];
    float* Ps = sm + 2 * BUFSZ;

    const int b   = blockIdx.z;
    const int h   = blockIdx.y;
    const int q0  = blockIdx.x * 64;
    const int kvh = h >> 2;
    const int tid  = threadIdx.x;
    const int warp = tid >> 5;
    const int lane = tid & 31;
    const int gid  = lane >> 2;     // 0..7
    const int tig  = lane & 3;      // 0..3

    const float scale = 0.08838834764831845f;   // 1/sqrt(128)

    // ---- Q fragments, pre-scaled, tf32, register resident ----
    uint32_t qf[16][4];
    {
        const float* qp  = Q + (size_t)(b * TSEQ + q0 + warp * 16 + gid) * CDIM + h * 128;
        const float* qp8 = qp + 8 * CDIM;
#pragma unroll
        for (int ks = 0; ks < 16; ks++) {
            qf[ks][0] = f2tf32(qp [ks * 8 + tig]     * scale);
            qf[ks][1] = f2tf32(qp8[ks * 8 + tig]     * scale);
            qf[ks][2] = f2tf32(qp [ks * 8 + tig + 4] * scale);
            qf[ks][3] = f2tf32(qp8[ks * 8 + tig + 4] * scale);
        }
    }

    float o[16][4];
#pragma unroll
    for (int nt = 0; nt < 16; nt++)
#pragma unroll
        for (int i = 0; i < 4; i++) o[nt][i] = 0.f;
    float m0 = -1e30f, m1 = -1e30f, l0 = 0.f, l1 = 0.f;

    const int nkt = q0 / 32 + 2;

    // loader indexing: idx = tid + i*128; r = idx>>5 (0..31), c4 = idx&31
    const int lr  = tid >> 2;            // unused granular; use per-iter compute
    (void)lr;

    // prefetch tile 0
    {
        float* Kb = sm;
        float* Vb = sm + KTILE;
#pragma unroll
        for (int i = 0; i < 8; i++) {
            int idx = tid + i * 128;
            int r = idx >> 5, c4 = idx & 31;
            const float* src = KV + (size_t)(b * TSEQ + r) * KVW + kvh * 128 + c4 * 4;
            cp_async16((uint32_t)__cvta_generic_to_shared(Kb + r * KPAD + c4 * 4), src);
            cp_async16((uint32_t)__cvta_generic_to_shared(Vb + r * VPAD + c4 * 4), src + NKV * HD);
        }
        asm volatile("cp.async.commit_group;\n" ::: "memory");
    }

    const int row0 = warp * 16 + gid;   // local row (0..63)

    for (int t = 0; t < nkt; t++) {
        const int buf = t & 1;
        // prefetch t+1 into buf^1 (safe: all threads passed end-of-iter barrier of t-1)
        if (t + 1 < nkt) {
            const int s1 = (t + 1) * 32;
            float* Kb = sm + (buf ^ 1) * BUFSZ;
            float* Vb = Kb + KTILE;
#pragma unroll
            for (int i = 0; i < 8; i++) {
                int idx = tid + i * 128;
                int r = idx >> 5, c4 = idx & 31;
                const float* src = KV + (size_t)(b * TSEQ + s1 + r) * KVW + kvh * 128 + c4 * 4;
                cp_async16((uint32_t)__cvta_generic_to_shared(Kb + r * KPAD + c4 * 4), src);
                cp_async16((uint32_t)__cvta_generic_to_shared(Vb + r * VPAD + c4 * 4), src + NKV * HD);
            }
        }
        asm volatile("cp.async.commit_group;\n" ::: "memory");
        asm volatile("cp.async.wait_group 1;\n" ::: "memory");
        __syncthreads();

        const float* Kb = sm + buf * BUFSZ;
        const float* Vb = Kb + KTILE;
        const int s0 = t * 32;

        // ---- S = Q K^T (warp: 16 rows x 32 keys) ----
        float s[4][4];
#pragma unroll
        for (int nt = 0; nt < 4; nt++)
#pragma unroll
            for (int i = 0; i < 4; i++) s[nt][i] = 0.f;

#pragma unroll
        for (int ks = 0; ks < 16; ks++) {
            const int kc = ks * 8;
#pragma unroll
            for (int nt = 0; nt < 4; nt++) {
                const float* kr = Kb + (nt * 8 + gid) * KPAD + kc + tig;
                uint32_t b0 = f2tf32(kr[0]);
                uint32_t b1 = f2tf32(kr[4]);
                mma_tf32(s[nt], qf[ks][0], qf[ks][1], qf[ks][2], qf[ks][3], b0, b1);
            }
        }

        // ---- causal mask (only the two diagonal tiles) ----
        if (t >= nkt - 2) {
            const int r0g = q0 + row0;
#pragma unroll
            for (int nt = 0; nt < 4; nt++) {
                const int c = s0 + nt * 8 + tig * 2;
                if (c > r0g)         s[nt][0] = -1e30f;
                if (c + 1 > r0g)     s[nt][1] = -1e30f;
                if (c > r0g + 8)     s[nt][2] = -1e30f;
                if (c + 1 > r0g + 8) s[nt][3] = -1e30f;
            }
        }

        // ---- online softmax ----
        float rm0 = s[0][0], rm1 = s[0][2];
#pragma unroll
        for (int nt = 0; nt < 4; nt++) {
            rm0 = fmaxf(rm0, fmaxf(s[nt][0], s[nt][1]));
            rm1 = fmaxf(rm1, fmaxf(s[nt][2], s[nt][3]));
        }
        rm0 = fmaxf(rm0, __shfl_xor_sync(0xffffffffu, rm0, 1));
        rm0 = fmaxf(rm0, __shfl_xor_sync(0xffffffffu, rm0, 2));
        rm1 = fmaxf(rm1, __shfl_xor_sync(0xffffffffu, rm1, 1));
        rm1 = fmaxf(rm1, __shfl_xor_sync(0xffffffffu, rm1, 2));

        float mt0 = fmaxf(m0, rm0), mt1 = fmaxf(m1, rm1);
        float c0 = __expf(m0 - mt0), c1 = __expf(m1 - mt1);
        m0 = mt0; m1 = mt1;

        float rs0 = 0.f, rs1 = 0.f;
#pragma unroll
        for (int nt = 0; nt < 4; nt++) {
            s[nt][0] = __expf(s[nt][0] - m0); rs0 += s[nt][0];
            s[nt][1] = __expf(s[nt][1] - m0); rs0 += s[nt][1];
            s[nt][2] = __expf(s[nt][2] - m1); rs1 += s[nt][2];
            s[nt][3] = __expf(s[nt][3] - m1); rs1 += s[nt][3];
        }
        rs0 += __shfl_xor_sync(0xffffffffu, rs0, 1);
        rs0 += __shfl_xor_sync(0xffffffffu, rs0, 2);
        rs1 += __shfl_xor_sync(0xffffffffu, rs1, 1);
        rs1 += __shfl_xor_sync(0xffffffffu, rs1, 2);
        l0 = l0 * c0 + rs0;
        l1 = l1 * c1 + rs1;

#pragma unroll
        for (int nt = 0; nt < 16; nt++) {
            o[nt][0] *= c0; o[nt][1] *= c0;
            o[nt][2] *= c1; o[nt][3] *= c1;
        }

        // ---- stage P to smem (warp-private region) ----
#pragma unroll
        for (int nt = 0; nt < 4; nt++) {
            *(float2*)&Ps[row0 * PPAD + nt * 8 + tig * 2]       = make_float2(s[nt][0], s[nt][1]);
            *(float2*)&Ps[(row0 + 8) * PPAD + nt * 8 + tig * 2] = make_float2(s[nt][2], s[nt][3]);
        }
        __syncwarp();

        // ---- O += P V ----
#pragma unroll
        for (int ks = 0; ks < 4; ks++) {
            const int kc = ks * 8;
            uint32_t a0 = f2tf32(Ps[row0 * PPAD + kc + tig]);
            uint32_t a1 = f2tf32(Ps[(row0 + 8) * PPAD + kc + tig]);
            uint32_t a2 = f2tf32(Ps[row0 * PPAD + kc + tig + 4]);
            uint32_t a3 = f2tf32(Ps[(row0 + 8) * PPAD + kc + tig + 4]);
#pragma unroll
            for (int nt = 0; nt < 16; nt++) {
                uint32_t b0 = f2tf32(Vb[(kc + tig) * VPAD + nt * 8 + gid]);
                uint32_t b1 = f2tf32(Vb[(kc + tig + 4) * VPAD + nt * 8 + gid]);
                mma_tf32(o[nt], a0, a1, a2, a3, b0, b1);
            }
        }
        __syncthreads();   // all reads of this buffer done before it is refilled
    }

    // ---- write out ----
    const float inv0 = 1.f / l0, inv1 = 1.f / l1;
    float* yp  = Y + (size_t)(b * TSEQ + q0 + row0) * CDIM + h * 128;
    float* yp8 = yp + 8 * CDIM;
#pragma unroll
    for (int nt = 0; nt < 16; nt++) {
        const int c = nt * 8 + tig * 2;
        *(float2*)&yp [c] = make_float2(o[nt][0] * inv0, o[nt][1] * inv0);
        *(float2*)&yp8[c] = make_float2(o[nt][2] * inv1, o[nt][3] * inv1);
    }
}

// ---------------------------------------------------------------------------
extern "C" void kernel_launch(void* const* d_in, const int* in_sizes, int n_in,
                              void* d_out, int out_size)
{
    const float* x   = (const float*)d_in[0];
    const float* Wq  = (const float*)d_in[1];
    const float* Wkv = (const float*)d_in[2];
    const float* Wo  = (const float*)d_in[3];
    float* out = (float*)d_out;

    float *pQ, *pKV, *pY;
    cudaGetSymbolAddress((void**)&pQ,  g_Q);
    cudaGetSymbolAddress((void**)&pKV, g_KV);
    cudaGetSymbolAddress((void**)&pY,  g_Y);

    const int gemm_smem = 4 * TILEF * sizeof(float);
    cudaFuncSetAttribute(gemm_tf32_nt, cudaFuncAttributeMaxDynamicSharedMemorySize, gemm_smem);
    cudaFuncSetAttribute(attn_mma_kernel, cudaFuncAttributeMaxDynamicSharedMemorySize, ATTN_SMEM);

    // 1) Q = x @ Wq^T
    gemm_tf32_nt<<<dim3(CDIM / 128, MROWS / 128), 256, gemm_smem>>>(x, Wq, pQ, MROWS, CDIM, CDIM);
    // 2) KV = x @ Wkv^T
    gemm_tf32_nt<<<dim3(KVW / 128, MROWS / 128), 256, gemm_smem>>>(x, Wkv, pKV, MROWS, KVW, CDIM);

    // 3) RoPE
    {
        int totQ = MROWS * NH * 64;
        rope_kernel<<<(totQ + 255) / 256, 256>>>(pQ, MROWS, NH, CDIM);
        int totK = MROWS * NKV * 64;
        rope_kernel<<<(totK + 255) / 256, 256>>>(pKV, MROWS, NKV, KVW);
    }

    // 4) tensor-core causal flash attention
    attn_mma_kernel<<<dim3(TSEQ / 64, NH, NB), 128, ATTN_SMEM>>>(pQ, pKV, pY);

    // 5) out = Y @ Wo^T
    gemm_tf32_nt<<<dim3(CDIM / 128, MROWS / 128), 256, gemm_smem>>>(pY, Wo, out, MROWS, CDIM, CDIM);
}